// round 1
// baseline (speedup 1.0000x reference)
#include <cuda_runtime.h>
#include <cuda_bf16.h>

#define D_MODEL 1024
#define VOCAB   32000
#define BATCH   4
#define SEQ     2048
#define M_TOT   (BATCH * SEQ)          // 8192
#define RESID_SCALE 0.1f
#define SOFTMAX_SCALE 0.03125f         // 1/sqrt(1024)

// ---------------- scratch (device globals; no allocation) ----------------
__device__ float g_X [M_TOT * D_MODEL];     // embeddings        32 MB
__device__ float g_Q [M_TOT * D_MODEL];
__device__ float g_K [M_TOT * D_MODEL];
__device__ float g_V [M_TOT * D_MODEL];
__device__ float g_S [(size_t)BATCH * SEQ * SEQ];  // scores/probs 64 MB
__device__ float g_X2[M_TOT * D_MODEL];     // x + 0.1*attn_out

// ---------------- embedding: x = tok_emb[idx] + pos_emb ----------------
__global__ void embed_kernel(const int* __restrict__ idx,
                             const float* __restrict__ tok,
                             const float* __restrict__ pos) {
    int row = blockIdx.x;            // 0..M_TOT-1
    int t   = row & (SEQ - 1);
    int token = idx[row];
    const float4* te = (const float4*)(tok + (size_t)token * D_MODEL);
    const float4* pe = (const float4*)(pos + (size_t)t * D_MODEL);
    float4* out = (float4*)(g_X + (size_t)row * D_MODEL);
    for (int i = threadIdx.x; i < D_MODEL / 4; i += blockDim.x) {
        float4 a = te[i], b = pe[i];
        out[i] = make_float4(a.x + b.x, a.y + b.y, a.z + b.z, a.w + b.w);
    }
}

// ---------------- tiled fp32 GEMM ----------------
// C[M,N] = A[M,K] @ op(B)
//   BT=true : B is [N,K] row-major (NT gemm, C=A*B^T)
//   BT=false: B is [K,N] row-major (NN gemm)
// EPI: 0 = plain, 1 = residual (C = resid + 0.1*acc), 2 = bias (C = acc + bias[n])
constexpr int BM = 128, BN = 128, BK = 16, TM = 8, TN = 8;

template<bool BT, int EPI>
__global__ void __launch_bounds__(256)
gemm_kernel(const float* __restrict__ A, const float* __restrict__ B,
            float* __restrict__ C, int M, int N, int K,
            long strideA, long strideB, long strideC,
            const float* __restrict__ extra) {
    __shared__ float As[BK][BM + 4];
    __shared__ float Bs[BK][BN + 4];

    const int bz = blockIdx.z;
    const float* Ab = A + strideA * bz;
    const float* Bb = B + strideB * bz;
    float*       Cb = C + strideC * bz;

    const int rowBase = blockIdx.y * BM;
    const int colBase = blockIdx.x * BN;
    const int tid = threadIdx.x;
    const int tm = tid / 16;   // 0..15
    const int tn = tid % 16;   // 0..15

    float acc[TM][TN];
#pragma unroll
    for (int i = 0; i < TM; i++)
#pragma unroll
        for (int j = 0; j < TN; j++) acc[i][j] = 0.f;

    const int numK = K / BK;
    for (int kt = 0; kt < numK; kt++) {
        const int k0 = kt * BK;
        // load A tile (128 rows x 16 k) -> As[k][m]
#pragma unroll
        for (int f = tid; f < BM * BK / 4; f += 256) {
            int r  = f >> 2;        // 0..127
            int c4 = f & 3;         // 0..3
            float4 v = *(const float4*)(Ab + (size_t)(rowBase + r) * K + k0 + c4 * 4);
            As[c4 * 4 + 0][r] = v.x;
            As[c4 * 4 + 1][r] = v.y;
            As[c4 * 4 + 2][r] = v.z;
            As[c4 * 4 + 3][r] = v.w;
        }
        // load B tile
        if (BT) {
#pragma unroll
            for (int f = tid; f < BN * BK / 4; f += 256) {
                int r  = f >> 2;
                int c4 = f & 3;
                float4 v = *(const float4*)(Bb + (size_t)(colBase + r) * K + k0 + c4 * 4);
                Bs[c4 * 4 + 0][r] = v.x;
                Bs[c4 * 4 + 1][r] = v.y;
                Bs[c4 * 4 + 2][r] = v.z;
                Bs[c4 * 4 + 3][r] = v.w;
            }
        } else {
#pragma unroll
            for (int f = tid; f < BK * BN / 4; f += 256) {
                int kk = f >> 5;        // 0..15
                int n4 = f & 31;        // 0..31
                float4 v = *(const float4*)(Bb + (size_t)(k0 + kk) * N + colBase + n4 * 4);
                *(float4*)&Bs[kk][n4 * 4] = v;
            }
        }
        __syncthreads();

#pragma unroll
        for (int kk = 0; kk < BK; kk++) {
            float4 a0 = *(const float4*)&As[kk][tm * TM];
            float4 a1 = *(const float4*)&As[kk][tm * TM + 4];
            float4 b0 = *(const float4*)&Bs[kk][tn * TN];
            float4 b1 = *(const float4*)&Bs[kk][tn * TN + 4];
            float a[TM] = {a0.x, a0.y, a0.z, a0.w, a1.x, a1.y, a1.z, a1.w};
            float b[TN] = {b0.x, b0.y, b0.z, b0.w, b1.x, b1.y, b1.z, b1.w};
#pragma unroll
            for (int i = 0; i < TM; i++)
#pragma unroll
                for (int j = 0; j < TN; j++)
                    acc[i][j] = fmaf(a[i], b[j], acc[i][j]);
        }
        __syncthreads();
    }

    // epilogue
#pragma unroll
    for (int i = 0; i < TM; i++) {
        size_t roff = (size_t)(rowBase + tm * TM + i) * N + colBase + tn * TN;
        float* cp = Cb + roff;
        float vals[TN];
        if (EPI == 0) {
#pragma unroll
            for (int j = 0; j < TN; j++) vals[j] = acc[i][j];
        } else if (EPI == 1) {
            const float* rp = extra + strideC * bz + roff;
            float4 r0 = *(const float4*)(rp);
            float4 r1 = *(const float4*)(rp + 4);
            float rr[TN] = {r0.x, r0.y, r0.z, r0.w, r1.x, r1.y, r1.z, r1.w};
#pragma unroll
            for (int j = 0; j < TN; j++) vals[j] = fmaf(RESID_SCALE, acc[i][j], rr[j]);
        } else {
            const float* bp = extra + colBase + tn * TN;
            float4 b0 = *(const float4*)(bp);
            float4 b1 = *(const float4*)(bp + 4);
            float bb[TN] = {b0.x, b0.y, b0.z, b0.w, b1.x, b1.y, b1.z, b1.w};
#pragma unroll
            for (int j = 0; j < TN; j++) vals[j] = acc[i][j] + bb[j];
        }
        *(float4*)(cp)     = make_float4(vals[0], vals[1], vals[2], vals[3]);
        *(float4*)(cp + 4) = make_float4(vals[4], vals[5], vals[6], vals[7]);
    }
}

// ---------------- causal softmax (in-place on g_S) ----------------
__global__ void softmax_kernel() {
    const int i = blockIdx.x;        // query row within batch
    const int b = blockIdx.y;
    float* s = g_S + ((size_t)b * SEQ + i) * SEQ;
    const int n = i + 1;             // valid causal length
    const int tid = threadIdx.x;
    __shared__ float red[256];

    float mx = -3.4e38f;
    for (int j = tid; j < n; j += 256) mx = fmaxf(mx, s[j]);
    red[tid] = mx; __syncthreads();
    for (int o = 128; o > 0; o >>= 1) {
        if (tid < o) red[tid] = fmaxf(red[tid], red[tid + o]);
        __syncthreads();
    }
    mx = red[0];
    __syncthreads();

    float sum = 0.f;
    for (int j = tid; j < n; j += 256) sum += __expf((s[j] - mx) * SOFTMAX_SCALE);
    red[tid] = sum; __syncthreads();
    for (int o = 128; o > 0; o >>= 1) {
        if (tid < o) red[tid] += red[tid + o];
        __syncthreads();
    }
    const float rinv = 1.f / red[0];
    __syncthreads();

    for (int j = tid; j < SEQ; j += 256)
        s[j] = (j < n) ? __expf((s[j] - mx) * SOFTMAX_SCALE) * rinv : 0.f;
}

// ---------------- launch ----------------
extern "C" void kernel_launch(void* const* d_in, const int* in_sizes, int n_in,
                              void* d_out, int out_size) {
    const int*   idx  = (const int*)  d_in[0];
    const float* tok  = (const float*)d_in[1];
    const float* pos  = (const float*)d_in[2];
    const float* Wq   = (const float*)d_in[3];
    const float* Wk   = (const float*)d_in[4];
    const float* Wv   = (const float*)d_in[5];
    const float* Wout = (const float*)d_in[6];
    const float* Wb   = (const float*)d_in[7];
    float* out = (float*)d_out;

    float *X, *Q, *K_, *V, *S, *X2;
    cudaGetSymbolAddress((void**)&X,  g_X);
    cudaGetSymbolAddress((void**)&Q,  g_Q);
    cudaGetSymbolAddress((void**)&K_, g_K);
    cudaGetSymbolAddress((void**)&V,  g_V);
    cudaGetSymbolAddress((void**)&S,  g_S);
    cudaGetSymbolAddress((void**)&X2, g_X2);

    // 1) embeddings
    embed_kernel<<<M_TOT, 256>>>(idx, tok, pos);

    // 2) QKV projections: [8192,1024] @ [1024,1024]^T
    dim3 gq(D_MODEL / BN, M_TOT / BM, 1);
    gemm_kernel<true, 0><<<gq, 256>>>(X, Wq, Q,  M_TOT, D_MODEL, D_MODEL, 0, 0, 0, nullptr);
    gemm_kernel<true, 0><<<gq, 256>>>(X, Wk, K_, M_TOT, D_MODEL, D_MODEL, 0, 0, 0, nullptr);
    gemm_kernel<true, 0><<<gq, 256>>>(X, Wv, V,  M_TOT, D_MODEL, D_MODEL, 0, 0, 0, nullptr);

    // 3) scores: per batch, Q[b] @ K[b]^T  -> S  [2048,2048]
    dim3 gs(SEQ / BN, SEQ / BM, BATCH);
    gemm_kernel<true, 0><<<gs, 256>>>(Q, K_, S, SEQ, SEQ, D_MODEL,
                                      (long)SEQ * D_MODEL, (long)SEQ * D_MODEL,
                                      (long)SEQ * SEQ, nullptr);

    // 4) causal softmax in place (scale folded in)
    softmax_kernel<<<dim3(SEQ, BATCH), 256>>>();

    // 5) attn_out = P @ V, fused residual: X2 = X + 0.1*attn_out
    dim3 gp(D_MODEL / BN, SEQ / BM, BATCH);
    gemm_kernel<false, 1><<<gp, 256>>>(S, V, X2, SEQ, D_MODEL, SEQ,
                                       (long)SEQ * SEQ, (long)SEQ * D_MODEL,
                                       (long)SEQ * D_MODEL, X);

    // 6) logits: [8192,1024] @ [32000,1024]^T + bias
    dim3 gl(VOCAB / BN, M_TOT / BM, 1);
    gemm_kernel<true, 2><<<gl, 256>>>(X2, Wout, out, M_TOT, VOCAB, D_MODEL,
                                      0, 0, 0, Wb);
}

// round 2
// speedup vs baseline: 1.6334x; 1.6334x over previous
#include <cuda_runtime.h>
#include <cuda_bf16.h>

#define D_MODEL 1024
#define VOCAB   32000
#define BATCH   4
#define SEQ     2048
#define M_TOT   (BATCH * SEQ)          // 8192
#define RESID_SCALE 0.1f
#define SOFTMAX_SCALE 0.03125f         // 1/sqrt(1024)

// ---------------- scratch (device globals; no allocation) ----------------
__device__ float g_X [M_TOT * D_MODEL];
__device__ float g_Q [M_TOT * D_MODEL];
__device__ float g_K [M_TOT * D_MODEL];
__device__ float g_V [M_TOT * D_MODEL];
__device__ float g_S [(size_t)BATCH * SEQ * SEQ];
__device__ float g_X2[M_TOT * D_MODEL];

// ---------------- embedding ----------------
__global__ void embed_kernel(const int* __restrict__ idx,
                             const float* __restrict__ tok,
                             const float* __restrict__ pos) {
    int row = blockIdx.x;
    int t   = row & (SEQ - 1);
    int token = idx[row];
    const float4* te = (const float4*)(tok + (size_t)token * D_MODEL);
    const float4* pe = (const float4*)(pos + (size_t)t * D_MODEL);
    float4* out = (float4*)(g_X + (size_t)row * D_MODEL);
    for (int i = threadIdx.x; i < D_MODEL / 4; i += blockDim.x) {
        float4 a = te[i], b = pe[i];
        out[i] = make_float4(a.x + b.x, a.y + b.y, a.z + b.z, a.w + b.w);
    }
}

// ---------------- causal softmax (in-place on g_S) ----------------
__global__ void softmax_kernel() {
    const int i = blockIdx.x;
    const int b = blockIdx.y;
    float* s = g_S + ((size_t)b * SEQ + i) * SEQ;
    const int n = i + 1;
    const int tid = threadIdx.x;
    __shared__ float red[256];

    float mx = -3.4e38f;
    for (int j = tid; j < n; j += 256) mx = fmaxf(mx, s[j]);
    red[tid] = mx; __syncthreads();
    for (int o = 128; o > 0; o >>= 1) {
        if (tid < o) red[tid] = fmaxf(red[tid], red[tid + o]);
        __syncthreads();
    }
    mx = red[0];
    __syncthreads();

    float sum = 0.f;
    for (int j = tid; j < n; j += 256) sum += __expf((s[j] - mx) * SOFTMAX_SCALE);
    red[tid] = sum; __syncthreads();
    for (int o = 128; o > 0; o >>= 1) {
        if (tid < o) red[tid] += red[tid + o];
        __syncthreads();
    }
    const float rinv = 1.f / red[0];
    __syncthreads();

    for (int j = tid; j < SEQ; j += 256)
        s[j] = (j < n) ? __expf((s[j] - mx) * SOFTMAX_SCALE) * rinv : 0.f;
}

// ---------------- TF32 tensor-core GEMM ----------------
// C[M,N] = A[M,K] @ op(B), fp32 in/out, tf32 mma with fp32 accumulate.
//   BT=true : B is [N,K] row-major (C = A @ B^T)
//   BT=false: B is [K,N] row-major (C = A @ B)
// EPI: 0 plain | 1 residual (C = extra + 0.1*acc) | 2 bias (C = acc + extra[n])
constexpr int BM = 128, BN = 128, BK = 32;
constexpr int SSTR   = BM + 8;          // 136: (k*8 + m) % 32 is lane-bijective
constexpr int TILE_F = BK * SSTR;       // floats per tile stage
constexpr int SMEM_BYTES = 2 * 2 * TILE_F * 4;   // 69632

__device__ __forceinline__ float f2tf32(float x) {
    unsigned r;
    asm("cvt.rna.tf32.f32 %0, %1;" : "=r"(r) : "f"(x));
    return __uint_as_float(r);
}

__device__ __forceinline__ void mma_tf32(float c[4], const unsigned a[4], const unsigned b[2]) {
    asm volatile(
        "mma.sync.aligned.m16n8k8.row.col.f32.tf32.tf32.f32 "
        "{%0,%1,%2,%3}, {%4,%5,%6,%7}, {%8,%9}, {%0,%1,%2,%3};\n"
        : "+f"(c[0]), "+f"(c[1]), "+f"(c[2]), "+f"(c[3])
        : "r"(a[0]), "r"(a[1]), "r"(a[2]), "r"(a[3]), "r"(b[0]), "r"(b[1]));
}

template<bool BT, int EPI>
__global__ void __launch_bounds__(256)
gemm_tc(const float* __restrict__ A, const float* __restrict__ B,
        float* __restrict__ C, int M, int N, int K,
        long strideA, long strideB, long strideC,
        const float* __restrict__ extra) {
    extern __shared__ float sh[];
    float* shA = sh;                 // [2][BK][SSTR]
    float* shB = sh + 2 * TILE_F;

    const int bz = blockIdx.z;
    const float* Ab = A + strideA * bz;
    const float* Bb = B + strideB * bz;
    float*       Cb = C + strideC * bz;

    const int rowBase = blockIdx.y * BM;
    const int colBase = blockIdx.x * BN;
    const int tid  = threadIdx.x;
    const int lane = tid & 31;
    const int warp = tid >> 5;
    const int wm = warp >> 2;        // 0..1  (64-row warp tile)
    const int wn = warp & 3;         // 0..3  (32-col warp tile)
    const int gr = lane >> 2;        // 0..7
    const int gc = lane & 3;         // 0..3

    float4 ra[4], rb[4];

    auto ldA = [&](int kt) {
        const int k0 = kt * BK;
#pragma unroll
        for (int i = 0; i < 4; i++) {
            int f = tid + i * 256;
            int r = f >> 3, kq = f & 7;
            ra[i] = *(const float4*)(Ab + (size_t)(rowBase + r) * K + k0 + kq * 4);
        }
    };
    auto stA = [&](int st) {
        float* s = shA + st * TILE_F;
#pragma unroll
        for (int i = 0; i < 4; i++) {
            int f = tid + i * 256;
            int r = f >> 3, kq = f & 7;
            s[(kq * 4 + 0) * SSTR + r] = f2tf32(ra[i].x);
            s[(kq * 4 + 1) * SSTR + r] = f2tf32(ra[i].y);
            s[(kq * 4 + 2) * SSTR + r] = f2tf32(ra[i].z);
            s[(kq * 4 + 3) * SSTR + r] = f2tf32(ra[i].w);
        }
    };
    auto ldB = [&](int kt) {
        const int k0 = kt * BK;
#pragma unroll
        for (int i = 0; i < 4; i++) {
            int f = tid + i * 256;
            if (BT) {
                int r = f >> 3, kq = f & 7;
                rb[i] = *(const float4*)(Bb + (size_t)(colBase + r) * K + k0 + kq * 4);
            } else {
                int kr = f >> 5, nq = f & 31;
                rb[i] = *(const float4*)(Bb + (size_t)(k0 + kr) * N + colBase + nq * 4);
            }
        }
    };
    auto stB = [&](int st) {
        float* s = shB + st * TILE_F;
#pragma unroll
        for (int i = 0; i < 4; i++) {
            int f = tid + i * 256;
            if (BT) {
                int r = f >> 3, kq = f & 7;
                s[(kq * 4 + 0) * SSTR + r] = f2tf32(rb[i].x);
                s[(kq * 4 + 1) * SSTR + r] = f2tf32(rb[i].y);
                s[(kq * 4 + 2) * SSTR + r] = f2tf32(rb[i].z);
                s[(kq * 4 + 3) * SSTR + r] = f2tf32(rb[i].w);
            } else {
                int kr = f >> 5, nq = f & 31;
                float* p = s + kr * SSTR + nq * 4;
                p[0] = f2tf32(rb[i].x);
                p[1] = f2tf32(rb[i].y);
                p[2] = f2tf32(rb[i].z);
                p[3] = f2tf32(rb[i].w);
            }
        }
    };

    float acc[4][4][4];
#pragma unroll
    for (int mi = 0; mi < 4; mi++)
#pragma unroll
        for (int ni = 0; ni < 4; ni++)
#pragma unroll
            for (int r = 0; r < 4; r++) acc[mi][ni][r] = 0.f;

    const int numK = K / BK;
    ldA(0); ldB(0);
    stA(0); stB(0);
    __syncthreads();

    for (int kt = 0; kt < numK; kt++) {
        const bool hasNext = (kt + 1 < numK);
        if (hasNext) { ldA(kt + 1); ldB(kt + 1); }

        const float* aS = shA + (kt & 1) * TILE_F;
        const float* bS = shB + (kt & 1) * TILE_F;
#pragma unroll
        for (int ks = 0; ks < 4; ks++) {
            const int kb = ks * 8;
            unsigned afr[4][4];
#pragma unroll
            for (int mi = 0; mi < 4; mi++) {
                int m = wm * 64 + mi * 16 + gr;
                afr[mi][0] = __float_as_uint(aS[(kb + gc)     * SSTR + m]);
                afr[mi][1] = __float_as_uint(aS[(kb + gc)     * SSTR + m + 8]);
                afr[mi][2] = __float_as_uint(aS[(kb + gc + 4) * SSTR + m]);
                afr[mi][3] = __float_as_uint(aS[(kb + gc + 4) * SSTR + m + 8]);
            }
            unsigned bfr[4][2];
#pragma unroll
            for (int ni = 0; ni < 4; ni++) {
                int n = wn * 32 + ni * 8 + gr;
                bfr[ni][0] = __float_as_uint(bS[(kb + gc)     * SSTR + n]);
                bfr[ni][1] = __float_as_uint(bS[(kb + gc + 4) * SSTR + n]);
            }
#pragma unroll
            for (int mi = 0; mi < 4; mi++)
#pragma unroll
                for (int ni = 0; ni < 4; ni++)
                    mma_tf32(acc[mi][ni], afr[mi], bfr[ni]);
        }

        if (hasNext) { stA((kt + 1) & 1); stB((kt + 1) & 1); }
        __syncthreads();
    }

    // epilogue: each thread owns float2 pairs at (row, col), (row+8, col)
#pragma unroll
    for (int mi = 0; mi < 4; mi++) {
#pragma unroll
        for (int ni = 0; ni < 4; ni++) {
            int row = rowBase + wm * 64 + mi * 16 + gr;
            int col = colBase + wn * 32 + ni * 8 + gc * 2;
            float v0 = acc[mi][ni][0], v1 = acc[mi][ni][1];
            float v2 = acc[mi][ni][2], v3 = acc[mi][ni][3];
            if (EPI == 1) {
                const float* rp0 = extra + strideC * bz + (size_t)row * N + col;
                const float* rp1 = extra + strideC * bz + (size_t)(row + 8) * N + col;
                float2 r0 = *(const float2*)rp0;
                float2 r1 = *(const float2*)rp1;
                v0 = fmaf(RESID_SCALE, v0, r0.x);
                v1 = fmaf(RESID_SCALE, v1, r0.y);
                v2 = fmaf(RESID_SCALE, v2, r1.x);
                v3 = fmaf(RESID_SCALE, v3, r1.y);
            } else if (EPI == 2) {
                float2 bb = *(const float2*)(extra + col);
                v0 += bb.x; v1 += bb.y; v2 += bb.x; v3 += bb.y;
            }
            *(float2*)(Cb + (size_t)row * N + col)       = make_float2(v0, v1);
            *(float2*)(Cb + (size_t)(row + 8) * N + col) = make_float2(v2, v3);
        }
    }
}

// ---------------- launch ----------------
extern "C" void kernel_launch(void* const* d_in, const int* in_sizes, int n_in,
                              void* d_out, int out_size) {
    const int*   idx  = (const int*)  d_in[0];
    const float* tok  = (const float*)d_in[1];
    const float* pos  = (const float*)d_in[2];
    const float* Wq   = (const float*)d_in[3];
    const float* Wk   = (const float*)d_in[4];
    const float* Wv   = (const float*)d_in[5];
    const float* Wout = (const float*)d_in[6];
    const float* Wb   = (const float*)d_in[7];
    float* out = (float*)d_out;

    float *X, *Q, *K_, *V, *S, *X2;
    cudaGetSymbolAddress((void**)&X,  g_X);
    cudaGetSymbolAddress((void**)&Q,  g_Q);
    cudaGetSymbolAddress((void**)&K_, g_K);
    cudaGetSymbolAddress((void**)&V,  g_V);
    cudaGetSymbolAddress((void**)&S,  g_S);
    cudaGetSymbolAddress((void**)&X2, g_X2);

    cudaFuncSetAttribute(gemm_tc<true, 0>,  cudaFuncAttributeMaxDynamicSharedMemorySize, SMEM_BYTES);
    cudaFuncSetAttribute(gemm_tc<false, 1>, cudaFuncAttributeMaxDynamicSharedMemorySize, SMEM_BYTES);
    cudaFuncSetAttribute(gemm_tc<true, 2>,  cudaFuncAttributeMaxDynamicSharedMemorySize, SMEM_BYTES);

    // 1) embeddings
    embed_kernel<<<M_TOT, 256>>>(idx, tok, pos);

    // 2) QKV projections
    dim3 gq(D_MODEL / BN, M_TOT / BM, 1);
    gemm_tc<true, 0><<<gq, 256, SMEM_BYTES>>>(X, Wq, Q,  M_TOT, D_MODEL, D_MODEL, 0, 0, 0, nullptr);
    gemm_tc<true, 0><<<gq, 256, SMEM_BYTES>>>(X, Wk, K_, M_TOT, D_MODEL, D_MODEL, 0, 0, 0, nullptr);
    gemm_tc<true, 0><<<gq, 256, SMEM_BYTES>>>(X, Wv, V,  M_TOT, D_MODEL, D_MODEL, 0, 0, 0, nullptr);

    // 3) scores: Q[b] @ K[b]^T
    dim3 gs(SEQ / BN, SEQ / BM, BATCH);
    gemm_tc<true, 0><<<gs, 256, SMEM_BYTES>>>(Q, K_, S, SEQ, SEQ, D_MODEL,
                                              (long)SEQ * D_MODEL, (long)SEQ * D_MODEL,
                                              (long)SEQ * SEQ, nullptr);

    // 4) causal softmax (scale folded in)
    softmax_kernel<<<dim3(SEQ, BATCH), 256>>>();

    // 5) attn_out = P @ V, fused residual
    dim3 gp(D_MODEL / BN, SEQ / BM, BATCH);
    gemm_tc<false, 1><<<gp, 256, SMEM_BYTES>>>(S, V, X2, SEQ, D_MODEL, SEQ,
                                               (long)SEQ * SEQ, (long)SEQ * D_MODEL,
                                               (long)SEQ * D_MODEL, X);

    // 6) logits + bias
    dim3 gl(VOCAB / BN, M_TOT / BM, 1);
    gemm_tc<true, 2><<<gl, 256, SMEM_BYTES>>>(X2, Wout, out, M_TOT, VOCAB, D_MODEL,
                                              0, 0, 0, Wb);
}

// round 4
// speedup vs baseline: 4.8197x; 2.9508x over previous
#include <cuda_runtime.h>
#include <cstdint>
#include <cstddef>

#define D_MODEL 1024
#define VOCAB   32000
#define BATCH   4
#define SEQ     2048
#define M_TOT   8192
#define QKV_N   3072
#define RESID_SCALE 0.1f
#define SOFTMAX_SCALE 0.03125f         // 1/sqrt(1024)

// ---------------- scratch (device globals; no allocation) ----------------
__device__ float g_X  [M_TOT * D_MODEL];            // fp32 embeddings (residual)
__device__ float g_Xr [M_TOT * D_MODEL];            // tf32-rounded embeddings
__device__ float g_QKV[(size_t)M_TOT * QKV_N];      // rounded Q|K|V (fused GEMM out)
__device__ float g_Vt [M_TOT * D_MODEL];            // V^T per batch [D_MODEL][SEQ]
__device__ float g_S  [(size_t)BATCH * SEQ * SEQ];  // scores / rounded probs
__device__ float g_X2 [M_TOT * D_MODEL];            // rounded (logits A)
__device__ float g_Wr [QKV_N * D_MODEL];            // rounded Wq|Wk|Wv stacked
__device__ float g_Wo [(size_t)VOCAB * D_MODEL];    // rounded Wout

// ---------------- helpers ----------------
__device__ __forceinline__ float f2tf32(float x) {
    unsigned r;
    asm("cvt.rna.tf32.f32 %0, %1;" : "=r"(r) : "f"(x));
    return __uint_as_float(r);
}
__device__ __forceinline__ uint32_t s2u(const void* p) {
    uint32_t a;
    asm("{ .reg .u64 t; cvta.to.shared.u64 t, %1; cvt.u32.u64 %0, t; }" : "=r"(a) : "l"(p));
    return a;
}
__device__ __forceinline__ uint32_t swz(uint32_t off) {   // SW128: bits[6:4] ^= bits[9:7]
    return off ^ ((off >> 3) & 0x70);
}
__device__ __forceinline__ void cp16(uint32_t dst, const void* src) {
    asm volatile("cp.async.cg.shared.global [%0], [%1], 16;" :: "r"(dst), "l"(src));
}
#define LDSM4(r, addr) \
    asm volatile("ldmatrix.sync.aligned.m8n8.x4.shared.b16 {%0,%1,%2,%3}, [%4];" \
                 : "=r"((r)[0]), "=r"((r)[1]), "=r"((r)[2]), "=r"((r)[3]) : "r"(addr))

__device__ __forceinline__ void mma_tf32(float c[4], const uint32_t a[4],
                                         uint32_t b0, uint32_t b1) {
    asm volatile(
        "mma.sync.aligned.m16n8k8.row.col.f32.tf32.tf32.f32 "
        "{%0,%1,%2,%3}, {%4,%5,%6,%7}, {%8,%9}, {%0,%1,%2,%3};\n"
        : "+f"(c[0]), "+f"(c[1]), "+f"(c[2]), "+f"(c[3])
        : "r"(a[0]), "r"(a[1]), "r"(a[2]), "r"(a[3]), "r"(b0), "r"(b1));
}

// ---------------- small kernels ----------------
__global__ void round_kernel(const float* __restrict__ in, float* __restrict__ out, int n4) {
    int i = blockIdx.x * blockDim.x + threadIdx.x;
    if (i < n4) {
        float4 v = ((const float4*)in)[i];
        v.x = f2tf32(v.x); v.y = f2tf32(v.y); v.z = f2tf32(v.z); v.w = f2tf32(v.w);
        ((float4*)out)[i] = v;
    }
}

__global__ void embed_kernel(const int* __restrict__ idx,
                             const float* __restrict__ tok,
                             const float* __restrict__ pos) {
    int row = blockIdx.x;
    int t   = row & (SEQ - 1);
    int token = idx[row];
    const float4* te = (const float4*)(tok + (size_t)token * D_MODEL);
    const float4* pe = (const float4*)(pos + (size_t)t * D_MODEL);
    float4* ox  = (float4*)(g_X  + (size_t)row * D_MODEL);
    float4* oxr = (float4*)(g_Xr + (size_t)row * D_MODEL);
    for (int i = threadIdx.x; i < D_MODEL / 4; i += blockDim.x) {
        float4 a = te[i], b = pe[i];
        float4 v = make_float4(a.x + b.x, a.y + b.y, a.z + b.z, a.w + b.w);
        ox[i] = v;
        oxr[i] = make_float4(f2tf32(v.x), f2tf32(v.y), f2tf32(v.z), f2tf32(v.w));
    }
}

// V slice of g_QKV [SEQ, QKV_N] -> Vt [D_MODEL, SEQ] per batch
__global__ void transpose_kernel() {
    __shared__ float t[32][33];
    int b  = blockIdx.z;
    int t0 = blockIdx.y * 32;   // seq
    int d0 = blockIdx.x * 32;   // dmodel
    const float* src = g_QKV + (size_t)b * SEQ * QKV_N + 2 * D_MODEL;
    float*       dst = g_Vt  + (size_t)b * D_MODEL * SEQ;
    int tx = threadIdx.x, ty = threadIdx.y;   // 32 x 8
#pragma unroll
    for (int j = 0; j < 32; j += 8)
        t[ty + j][tx] = src[(size_t)(t0 + ty + j) * QKV_N + d0 + tx];
    __syncthreads();
#pragma unroll
    for (int j = 0; j < 32; j += 8)
        dst[(size_t)(d0 + ty + j) * SEQ + t0 + tx] = t[tx][ty + j];
}

__global__ void softmax_kernel() {
    const int i = blockIdx.x;
    const int b = blockIdx.y;
    float* s = g_S + ((size_t)b * SEQ + i) * SEQ;
    const int n = i + 1;
    const int tid = threadIdx.x;
    __shared__ float red[256];

    float mx = -3.4e38f;
    for (int j = tid; j < n; j += 256) mx = fmaxf(mx, s[j]);
    red[tid] = mx; __syncthreads();
    for (int o = 128; o > 0; o >>= 1) {
        if (tid < o) red[tid] = fmaxf(red[tid], red[tid + o]);
        __syncthreads();
    }
    mx = red[0];
    __syncthreads();

    float sum = 0.f;
    for (int j = tid; j < n; j += 256) sum += __expf((s[j] - mx) * SOFTMAX_SCALE);
    red[tid] = sum; __syncthreads();
    for (int o = 128; o > 0; o >>= 1) {
        if (tid < o) red[tid] += red[tid + o];
        __syncthreads();
    }
    const float rinv = 1.f / red[0];
    __syncthreads();

    for (int j = tid; j < SEQ; j += 256)
        s[j] = (j < n) ? f2tf32(__expf((s[j] - mx) * SOFTMAX_SCALE) * rinv) : 0.f;
}

// ---------------- TF32 mma.sync GEMM, cp.async + ldmatrix ----------------
// C[M,N] = A[M,K] @ B[N,K]^T, both K-major row-major, values pre-rounded to tf32.
// EPI: 0 plain | 1 round | 2 residual+round | 3 bias
// CAUSAL: 0 none | 1 skip tiles above diagonal | 2 K-limit at diagonal
constexpr int BM = 128, BN = 128, BK = 32;          // BK f32 = 128B SW128 row
constexpr int A_BYTES = BM * 128;                   // 16 KB
constexpr int STG = 2 * A_BYTES;                    // 32 KB per stage (A|B)
constexpr int GSMEM = 2 * STG;                      // 64 KB

template<int EPI, int CAUSAL>
__global__ void __launch_bounds__(256, 2)
gemm_mma(const float* __restrict__ A, const float* __restrict__ B, float* __restrict__ C,
         int lda, int ldb, int ldc, int kLen,
         long sA, long sB, long sC, const float* __restrict__ extra) {
    extern __shared__ char smem[];
    const int bz = blockIdx.z;
    const int rowBase = blockIdx.y * BM;
    const int colBase = blockIdx.x * BN;
    if (CAUSAL == 1 && colBase > rowBase + BM - 1) return;

    const float* Ab = A + sA * bz;
    const float* Bb = B + sB * bz;
    float*       Cb = C + sC * bz;

    const int numK = (CAUSAL == 2 ? (rowBase + BM) : kLen) / BK;
    const uint32_t sb = s2u(smem);
    const int tid = threadIdx.x, lane = tid & 31, warp = tid >> 5;
    const int wm = warp >> 2, wn = warp & 3;   // warp tile 64x32

    // cp.async staging indices: thread -> (row cr + j*32, 16B chunk cc)
    const int cr = tid >> 3;    // 0..31
    const int cc = tid & 7;     // 0..7

    auto issue = [&](int kt) {
        const uint32_t st = sb + (kt & 1) * STG;
        const int k0 = kt * BK;
        const float* as = Ab + (size_t)(rowBase + cr) * lda + k0 + cc * 4;
        const float* bs = Bb + (size_t)(colBase + cr) * ldb + k0 + cc * 4;
#pragma unroll
        for (int j = 0; j < 4; j++) {
            uint32_t so = swz((cr + j * 32) * 128 + cc * 16);
            cp16(st + so,           as + (size_t)j * 32 * lda);
            cp16(st + A_BYTES + so, bs + (size_t)j * 32 * ldb);
        }
        asm volatile("cp.async.commit_group;");
    };

    // ldmatrix per-lane base offsets (unswizzled; swz applied after +ks*32)
    const uint32_t aoff = (uint32_t)((wm * 64 + (lane & 15)) * 128 + (lane >> 4) * 16);
    const uint32_t boff = (uint32_t)((wn * 32 + (lane >> 4) * 8 + (lane & 7)) * 128
                                     + ((lane >> 3) & 1) * 16);

    float acc[4][4][4];
#pragma unroll
    for (int mi = 0; mi < 4; mi++)
#pragma unroll
        for (int ni = 0; ni < 4; ni++)
#pragma unroll
            for (int r = 0; r < 4; r++) acc[mi][ni][r] = 0.f;

    issue(0);
    if (numK > 1) issue(1);

    for (int kt = 0; kt < numK; kt++) {
        if (kt + 1 < numK) asm volatile("cp.async.wait_group 1;");
        else               asm volatile("cp.async.wait_group 0;");
        __syncthreads();

        const uint32_t stA = sb + (kt & 1) * STG;
        const uint32_t stB = stA + A_BYTES;
#pragma unroll
        for (int ks = 0; ks < 4; ks++) {
            uint32_t a[4][4];
#pragma unroll
            for (int mi = 0; mi < 4; mi++)
                LDSM4(a[mi], stA + swz(aoff + mi * 2048 + ks * 32));
            uint32_t b[2][4];
#pragma unroll
            for (int p = 0; p < 2; p++)
                LDSM4(b[p], stB + swz(boff + p * 2048 + ks * 32));
#pragma unroll
            for (int mi = 0; mi < 4; mi++) {
                mma_tf32(acc[mi][0], a[mi], b[0][0], b[0][1]);
                mma_tf32(acc[mi][1], a[mi], b[0][2], b[0][3]);
                mma_tf32(acc[mi][2], a[mi], b[1][0], b[1][1]);
                mma_tf32(acc[mi][3], a[mi], b[1][2], b[1][3]);
            }
        }
        __syncthreads();
        if (kt + 2 < numK) issue(kt + 2);
    }

    // epilogue: c0,c1 = (row, col..col+1); c2,c3 = (row+8, col..col+1)
    const int gr = lane >> 2, gc = lane & 3;
#pragma unroll
    for (int mi = 0; mi < 4; mi++) {
#pragma unroll
        for (int ni = 0; ni < 4; ni++) {
            int row = rowBase + wm * 64 + mi * 16 + gr;
            int col = colBase + wn * 32 + ni * 8 + gc * 2;
            float v0 = acc[mi][ni][0], v1 = acc[mi][ni][1];
            float v2 = acc[mi][ni][2], v3 = acc[mi][ni][3];
            if (EPI == 1) {
                v0 = f2tf32(v0); v1 = f2tf32(v1); v2 = f2tf32(v2); v3 = f2tf32(v3);
            } else if (EPI == 2) {
                const float* x0 = extra + sC * bz + (size_t)row * ldc + col;
                float2 r0 = *(const float2*)x0;
                float2 r1 = *(const float2*)(x0 + (size_t)8 * ldc);
                v0 = f2tf32(fmaf(RESID_SCALE, v0, r0.x));
                v1 = f2tf32(fmaf(RESID_SCALE, v1, r0.y));
                v2 = f2tf32(fmaf(RESID_SCALE, v2, r1.x));
                v3 = f2tf32(fmaf(RESID_SCALE, v3, r1.y));
            } else if (EPI == 3) {
                float2 bb = *(const float2*)(extra + col);
                v0 += bb.x; v1 += bb.y; v2 += bb.x; v3 += bb.y;
            }
            *(float2*)(Cb + (size_t)row * ldc + col)       = make_float2(v0, v1);
            *(float2*)(Cb + (size_t)(row + 8) * ldc + col) = make_float2(v2, v3);
        }
    }
}

// ---------------- launch ----------------
extern "C" void kernel_launch(void* const* d_in, const int* in_sizes, int n_in,
                              void* d_out, int out_size) {
    const int*   idx  = (const int*)  d_in[0];
    const float* tok  = (const float*)d_in[1];
    const float* pos  = (const float*)d_in[2];
    const float* Wq   = (const float*)d_in[3];
    const float* Wk   = (const float*)d_in[4];
    const float* Wv   = (const float*)d_in[5];
    const float* Wout = (const float*)d_in[6];
    const float* Wb   = (const float*)d_in[7];
    float* out = (float*)d_out;

    float *X, *Xr, *QKV, *Vt, *S, *X2, *Wr, *Wo;
    cudaGetSymbolAddress((void**)&X,   g_X);
    cudaGetSymbolAddress((void**)&Xr,  g_Xr);
    cudaGetSymbolAddress((void**)&QKV, g_QKV);
    cudaGetSymbolAddress((void**)&Vt,  g_Vt);
    cudaGetSymbolAddress((void**)&S,   g_S);
    cudaGetSymbolAddress((void**)&X2,  g_X2);
    cudaGetSymbolAddress((void**)&Wr,  g_Wr);
    cudaGetSymbolAddress((void**)&Wo,  g_Wo);

    cudaFuncSetAttribute(gemm_mma<1, 0>, cudaFuncAttributeMaxDynamicSharedMemorySize, GSMEM);
    cudaFuncSetAttribute(gemm_mma<0, 1>, cudaFuncAttributeMaxDynamicSharedMemorySize, GSMEM);
    cudaFuncSetAttribute(gemm_mma<2, 2>, cudaFuncAttributeMaxDynamicSharedMemorySize, GSMEM);
    cudaFuncSetAttribute(gemm_mma<3, 0>, cudaFuncAttributeMaxDynamicSharedMemorySize, GSMEM);

    // 0) pre-round weights to tf32 (Wq|Wk|Wv stacked)
    const int wn4 = D_MODEL * D_MODEL / 4;
    round_kernel<<<(wn4 + 255) / 256, 256>>>(Wq, Wr,                         wn4);
    round_kernel<<<(wn4 + 255) / 256, 256>>>(Wk, Wr +     D_MODEL * D_MODEL, wn4);
    round_kernel<<<(wn4 + 255) / 256, 256>>>(Wv, Wr + 2 * D_MODEL * D_MODEL, wn4);
    const int on4 = VOCAB * D_MODEL / 4;
    round_kernel<<<(on4 + 255) / 256, 256>>>(Wout, Wo, on4);

    // 1) embeddings
    embed_kernel<<<M_TOT, 256>>>(idx, tok, pos);

    // 2) fused QKV: [8192,1024] @ [3072,1024]^T -> g_QKV (rounded)
    dim3 gq(QKV_N / BN, M_TOT / BM, 1);
    gemm_mma<1, 0><<<gq, 256, GSMEM>>>(Xr, Wr, QKV, D_MODEL, D_MODEL, QKV_N, D_MODEL,
                                       0, 0, 0, nullptr);

    // 3) V transpose per batch
    transpose_kernel<<<dim3(D_MODEL / 32, SEQ / 32, BATCH), dim3(32, 8)>>>();

    // 4) scores: Q @ K^T, lower-triangle tiles only
    dim3 gs(SEQ / BN, SEQ / BM, BATCH);
    gemm_mma<0, 1><<<gs, 256, GSMEM>>>(QKV, QKV + D_MODEL, S,
                                       QKV_N, QKV_N, SEQ, D_MODEL,
                                       (long)SEQ * QKV_N, (long)SEQ * QKV_N,
                                       (long)SEQ * SEQ, nullptr);

    // 5) causal softmax (rounds probs)
    softmax_kernel<<<dim3(SEQ, BATCH), 256>>>();

    // 6) attn_out = P @ Vt^T, fused residual + round, K truncated at diagonal
    dim3 gp(D_MODEL / BN, SEQ / BM, BATCH);
    gemm_mma<2, 2><<<gp, 256, GSMEM>>>(S, Vt, X2, SEQ, SEQ, D_MODEL, SEQ,
                                       (long)SEQ * SEQ, (long)D_MODEL * SEQ,
                                       (long)SEQ * D_MODEL, X);

    // 7) logits: X2 @ Wout^T + bias
    dim3 gl(VOCAB / BN, M_TOT / BM, 1);
    gemm_mma<3, 0><<<gl, 256, GSMEM>>>(X2, Wo, out, D_MODEL, D_MODEL, VOCAB, D_MODEL,
                                       0, 0, 0, Wb);
}

// round 5
// speedup vs baseline: 5.2427x; 1.0878x over previous
#include <cuda_runtime.h>
#include <cuda_fp16.h>
#include <cstdint>
#include <cstddef>

#define D_MODEL 1024
#define VOCAB   32000
#define BATCH   4
#define SEQ     2048
#define M_TOT   8192
#define QKV_N   3072
#define RESID_SCALE 0.1f
#define SOFTMAX_SCALE 0.03125f         // 1/sqrt(1024)

// ---------------- scratch (device globals; no allocation) ----------------
__device__ float  g_X  [M_TOT * D_MODEL];            // fp32 embeddings (residual)
__device__ __half g_Xh [M_TOT * D_MODEL];            // half embeddings (GEMM A)
__device__ __half g_QKV[(size_t)M_TOT * QKV_N];      // half Q|K|V
__device__ __half g_Vt [M_TOT * D_MODEL];            // V^T per batch [D_MODEL][SEQ]
__device__ float  g_S  [(size_t)BATCH * SEQ * SEQ];  // fp32 raw scores
__device__ __half g_Sh [(size_t)BATCH * SEQ * SEQ];  // half probs
__device__ __half g_X2 [M_TOT * D_MODEL];            // half (logits A)
__device__ __half g_Wr [QKV_N * D_MODEL];            // half Wq|Wk|Wv stacked
__device__ __half g_Wo [(size_t)VOCAB * D_MODEL];    // half Wout

// ---------------- helpers ----------------
__device__ __forceinline__ uint32_t s2u(const void* p) {
    uint32_t a;
    asm("{ .reg .u64 t; cvta.to.shared.u64 t, %1; cvt.u32.u64 %0, t; }" : "=r"(a) : "l"(p));
    return a;
}
__device__ __forceinline__ uint32_t swz(uint32_t off) {   // SW128
    return off ^ ((off >> 3) & 0x70);
}
__device__ __forceinline__ void cp16(uint32_t dst, const void* src) {
    asm volatile("cp.async.cg.shared.global [%0], [%1], 16;" :: "r"(dst), "l"(src));
}
#define LDSM4(r, addr) \
    asm volatile("ldmatrix.sync.aligned.m8n8.x4.shared.b16 {%0,%1,%2,%3}, [%4];" \
                 : "=r"((r)[0]), "=r"((r)[1]), "=r"((r)[2]), "=r"((r)[3]) : "r"(addr))

__device__ __forceinline__ void mma_f16(float c[4], const uint32_t a[4],
                                        uint32_t b0, uint32_t b1) {
    asm volatile(
        "mma.sync.aligned.m16n8k16.row.col.f32.f16.f16.f32 "
        "{%0,%1,%2,%3}, {%4,%5,%6,%7}, {%8,%9}, {%0,%1,%2,%3};\n"
        : "+f"(c[0]), "+f"(c[1]), "+f"(c[2]), "+f"(c[3])
        : "r"(a[0]), "r"(a[1]), "r"(a[2]), "r"(a[3]), "r"(b0), "r"(b1));
}

// ---------------- small kernels ----------------
__global__ void round_kernel(const float* __restrict__ in, __half* __restrict__ out, int n4) {
    int i = blockIdx.x * blockDim.x + threadIdx.x;
    if (i < n4) {
        float4 v = ((const float4*)in)[i];
        __half2* o = (__half2*)(out + (size_t)i * 4);
        o[0] = __floats2half2_rn(v.x, v.y);
        o[1] = __floats2half2_rn(v.z, v.w);
    }
}

__global__ void embed_kernel(const int* __restrict__ idx,
                             const float* __restrict__ tok,
                             const float* __restrict__ pos) {
    int row = blockIdx.x;
    int t   = row & (SEQ - 1);
    int token = idx[row];
    const float4* te = (const float4*)(tok + (size_t)token * D_MODEL);
    const float4* pe = (const float4*)(pos + (size_t)t * D_MODEL);
    float4*  ox = (float4*)(g_X + (size_t)row * D_MODEL);
    __half2* oh = (__half2*)(g_Xh + (size_t)row * D_MODEL);
    for (int i = threadIdx.x; i < D_MODEL / 4; i += blockDim.x) {
        float4 a = te[i], b = pe[i];
        float4 v = make_float4(a.x + b.x, a.y + b.y, a.z + b.z, a.w + b.w);
        ox[i] = v;
        oh[i * 2]     = __floats2half2_rn(v.x, v.y);
        oh[i * 2 + 1] = __floats2half2_rn(v.z, v.w);
    }
}

// V slice of g_QKV [SEQ, QKV_N] -> Vt [D_MODEL, SEQ] per batch (half)
__global__ void transpose_kernel() {
    __shared__ __half t[32][34];
    int b  = blockIdx.z;
    int t0 = blockIdx.y * 32;   // seq
    int d0 = blockIdx.x * 32;   // dmodel
    const __half* src = g_QKV + (size_t)b * SEQ * QKV_N + 2 * D_MODEL;
    __half*       dst = g_Vt  + (size_t)b * D_MODEL * SEQ;
    int tx = threadIdx.x, ty = threadIdx.y;   // 32 x 8
#pragma unroll
    for (int j = 0; j < 32; j += 8)
        t[ty + j][tx] = src[(size_t)(t0 + ty + j) * QKV_N + d0 + tx];
    __syncthreads();
#pragma unroll
    for (int j = 0; j < 32; j += 8)
        dst[(size_t)(d0 + ty + j) * SEQ + t0 + tx] = t[tx][ty + j];
}

__global__ void softmax_kernel() {
    const int i = blockIdx.x;
    const int b = blockIdx.y;
    const float* s = g_S  + ((size_t)b * SEQ + i) * SEQ;
    __half*     so = g_Sh + ((size_t)b * SEQ + i) * SEQ;
    const int n = i + 1;
    const int tid = threadIdx.x;
    __shared__ float red[256];

    float mx = -3.4e38f;
    for (int j = tid; j < n; j += 256) mx = fmaxf(mx, s[j]);
    red[tid] = mx; __syncthreads();
    for (int o = 128; o > 0; o >>= 1) {
        if (tid < o) red[tid] = fmaxf(red[tid], red[tid + o]);
        __syncthreads();
    }
    mx = red[0];
    __syncthreads();

    float sum = 0.f;
    for (int j = tid; j < n; j += 256) sum += __expf((s[j] - mx) * SOFTMAX_SCALE);
    red[tid] = sum; __syncthreads();
    for (int o = 128; o > 0; o >>= 1) {
        if (tid < o) red[tid] += red[tid + o];
        __syncthreads();
    }
    const float rinv = 1.f / red[0];
    __syncthreads();

    for (int j = tid; j < SEQ; j += 256)
        so[j] = (j < n) ? __float2half_rn(__expf((s[j] - mx) * SOFTMAX_SCALE) * rinv)
                        : __half(0.f);
}

// ---------------- FP16 mma.sync GEMM, 3-stage cp.async + ldmatrix ----------------
// C[M,N] = A[M,K] @ B[N,K]^T, A/B half K-major.
// EPI: 0 fp32 out | 1 half out | 2 half out, residual from extra(fp32) | 3 fp32 out + bias
// CAUSAL: 0 none | 1 skip tiles above diagonal | 2 K-limit at diagonal
constexpr int BM = 128, BN = 256, BK = 64;          // BK halves = 128B SW128 row
constexpr int A_BYTES = BM * 128;                   // 16 KB
constexpr int B_BYTES = BN * 128;                   // 32 KB
constexpr int STG = A_BYTES + B_BYTES;              // 48 KB
constexpr int GSMEM = 3 * STG;                      // 144 KB

template<int EPI, int CAUSAL>
__global__ void __launch_bounds__(512, 1)
gemm_h(const __half* __restrict__ A, const __half* __restrict__ B, void* __restrict__ Cv,
       int lda, int ldb, int ldc, int kLen,
       long sA, long sB, long sC, const float* __restrict__ extra) {
    extern __shared__ char smem[];
    const int bz = blockIdx.z;
    const int rowBase = blockIdx.y * BM;
    const int colBase = blockIdx.x * BN;
    if (CAUSAL == 1 && colBase > rowBase + BM - 1) return;

    const __half* Ab = A + sA * bz;
    const __half* Bb = B + sB * bz;

    const int numK = (CAUSAL == 2 ? (rowBase + BM) : kLen) / BK;
    const uint32_t sb = s2u(smem);
    const int tid = threadIdx.x, lane = tid & 31, warp = tid >> 5;
    const int wm = warp >> 3, wn = warp & 7;   // 2 x 8 warps, warp tile 64x32

    const int cr = tid >> 3;    // 0..63
    const int cc = tid & 7;     // 0..7 (16B chunk)

    auto issue = [&](int kt) {
        const uint32_t st = sb + (kt % 3) * STG;
        const int k0 = kt * BK;
        const __half* as = Ab + (size_t)(rowBase + cr) * lda + k0 + cc * 8;
        const __half* bs = Bb + (size_t)(colBase + cr) * ldb + k0 + cc * 8;
#pragma unroll
        for (int j = 0; j < 2; j++)
            cp16(st + swz((cr + j * 64) * 128 + cc * 16), as + (size_t)j * 64 * lda);
#pragma unroll
        for (int j = 0; j < 4; j++)
            cp16(st + A_BYTES + swz((cr + j * 64) * 128 + cc * 16), bs + (size_t)j * 64 * ldb);
        asm volatile("cp.async.commit_group;");
    };

    // ldmatrix per-lane base offsets (pre-swizzle)
    const uint32_t aoff = (uint32_t)((wm * 64 + (lane & 15)) * 128 + (lane >> 4) * 16);
    const uint32_t boff = (uint32_t)((wn * 32 + (lane & 7) + ((lane >> 4) & 1) * 8) * 128
                                     + ((lane >> 3) & 1) * 16);

    float acc[4][4][4];
#pragma unroll
    for (int mi = 0; mi < 4; mi++)
#pragma unroll
        for (int ni = 0; ni < 4; ni++)
#pragma unroll
            for (int r = 0; r < 4; r++) acc[mi][ni][r] = 0.f;

    issue(0);
    if (numK > 1) issue(1);
    if (numK > 2) issue(2);

    for (int kt = 0; kt < numK; kt++) {
        const int rem = numK - kt - 1;
        if (rem >= 2)      asm volatile("cp.async.wait_group 2;");
        else if (rem == 1) asm volatile("cp.async.wait_group 1;");
        else               asm volatile("cp.async.wait_group 0;");
        __syncthreads();

        const uint32_t stA = sb + (kt % 3) * STG;
        const uint32_t stB = stA + A_BYTES;
#pragma unroll
        for (int ks = 0; ks < 4; ks++) {
            uint32_t a[4][4];
#pragma unroll
            for (int mi = 0; mi < 4; mi++)
                LDSM4(a[mi], stA + swz(aoff + mi * 2048 + ks * 32));
            uint32_t bq[2][4];
#pragma unroll
            for (int p = 0; p < 2; p++)
                LDSM4(bq[p], stB + swz(boff + p * 2048 + ks * 32));
#pragma unroll
            for (int mi = 0; mi < 4; mi++) {
                mma_f16(acc[mi][0], a[mi], bq[0][0], bq[0][1]);
                mma_f16(acc[mi][1], a[mi], bq[0][2], bq[0][3]);
                mma_f16(acc[mi][2], a[mi], bq[1][0], bq[1][1]);
                mma_f16(acc[mi][3], a[mi], bq[1][2], bq[1][3]);
            }
        }
        __syncthreads();
        if (kt + 3 < numK) issue(kt + 3);
    }

    // epilogue
    const int gr = lane >> 2, gc = lane & 3;
#pragma unroll
    for (int mi = 0; mi < 4; mi++) {
#pragma unroll
        for (int ni = 0; ni < 4; ni++) {
            int row = rowBase + wm * 64 + mi * 16 + gr;
            int col = colBase + wn * 32 + ni * 8 + gc * 2;
            float v0 = acc[mi][ni][0], v1 = acc[mi][ni][1];
            float v2 = acc[mi][ni][2], v3 = acc[mi][ni][3];
            if (EPI == 0) {
                float* Cb = (float*)Cv + sC * bz;
                *(float2*)(Cb + (size_t)row * ldc + col)       = make_float2(v0, v1);
                *(float2*)(Cb + (size_t)(row + 8) * ldc + col) = make_float2(v2, v3);
            } else if (EPI == 1) {
                __half* Cb = (__half*)Cv + sC * bz;
                *(__half2*)(Cb + (size_t)row * ldc + col)       = __floats2half2_rn(v0, v1);
                *(__half2*)(Cb + (size_t)(row + 8) * ldc + col) = __floats2half2_rn(v2, v3);
            } else if (EPI == 2) {
                __half* Cb = (__half*)Cv + sC * bz;
                const float* x0 = extra + sC * bz + (size_t)row * ldc + col;
                float2 r0 = *(const float2*)x0;
                float2 r1 = *(const float2*)(x0 + (size_t)8 * ldc);
                *(__half2*)(Cb + (size_t)row * ldc + col) =
                    __floats2half2_rn(fmaf(RESID_SCALE, v0, r0.x), fmaf(RESID_SCALE, v1, r0.y));
                *(__half2*)(Cb + (size_t)(row + 8) * ldc + col) =
                    __floats2half2_rn(fmaf(RESID_SCALE, v2, r1.x), fmaf(RESID_SCALE, v3, r1.y));
            } else {
                float* Cb = (float*)Cv + sC * bz;
                float2 bb = *(const float2*)(extra + col);
                *(float2*)(Cb + (size_t)row * ldc + col)       = make_float2(v0 + bb.x, v1 + bb.y);
                *(float2*)(Cb + (size_t)(row + 8) * ldc + col) = make_float2(v2 + bb.x, v3 + bb.y);
            }
        }
    }
}

// ---------------- launch ----------------
extern "C" void kernel_launch(void* const* d_in, const int* in_sizes, int n_in,
                              void* d_out, int out_size) {
    const int*   idx  = (const int*)  d_in[0];
    const float* tok  = (const float*)d_in[1];
    const float* pos  = (const float*)d_in[2];
    const float* Wq   = (const float*)d_in[3];
    const float* Wk   = (const float*)d_in[4];
    const float* Wv   = (const float*)d_in[5];
    const float* Wout = (const float*)d_in[6];
    const float* Wb   = (const float*)d_in[7];

    float *X, *S;
    __half *Xh, *QKV, *Vt, *Sh, *X2, *Wr, *Wo;
    cudaGetSymbolAddress((void**)&X,   g_X);
    cudaGetSymbolAddress((void**)&Xh,  g_Xh);
    cudaGetSymbolAddress((void**)&QKV, g_QKV);
    cudaGetSymbolAddress((void**)&Vt,  g_Vt);
    cudaGetSymbolAddress((void**)&S,   g_S);
    cudaGetSymbolAddress((void**)&Sh,  g_Sh);
    cudaGetSymbolAddress((void**)&X2,  g_X2);
    cudaGetSymbolAddress((void**)&Wr,  g_Wr);
    cudaGetSymbolAddress((void**)&Wo,  g_Wo);

    cudaFuncSetAttribute(gemm_h<1, 0>, cudaFuncAttributeMaxDynamicSharedMemorySize, GSMEM);
    cudaFuncSetAttribute(gemm_h<0, 1>, cudaFuncAttributeMaxDynamicSharedMemorySize, GSMEM);
    cudaFuncSetAttribute(gemm_h<2, 2>, cudaFuncAttributeMaxDynamicSharedMemorySize, GSMEM);
    cudaFuncSetAttribute(gemm_h<3, 0>, cudaFuncAttributeMaxDynamicSharedMemorySize, GSMEM);

    // 0) weights -> half
    const int wn4 = D_MODEL * D_MODEL / 4;
    round_kernel<<<(wn4 + 255) / 256, 256>>>(Wq, Wr,                         wn4);
    round_kernel<<<(wn4 + 255) / 256, 256>>>(Wk, Wr +     D_MODEL * D_MODEL, wn4);
    round_kernel<<<(wn4 + 255) / 256, 256>>>(Wv, Wr + 2 * D_MODEL * D_MODEL, wn4);
    const int on4 = VOCAB * D_MODEL / 4;
    round_kernel<<<(on4 + 255) / 256, 256>>>(Wout, Wo, on4);

    // 1) embeddings
    embed_kernel<<<M_TOT, 256>>>(idx, tok, pos);

    // 2) fused QKV: [8192,1024] @ [3072,1024]^T -> half
    dim3 gq(QKV_N / BN, M_TOT / BM, 1);
    gemm_h<1, 0><<<gq, 512, GSMEM>>>(Xh, Wr, QKV, D_MODEL, D_MODEL, QKV_N, D_MODEL,
                                     0, 0, 0, nullptr);

    // 3) V transpose per batch
    transpose_kernel<<<dim3(D_MODEL / 32, SEQ / 32, BATCH), dim3(32, 8)>>>();

    // 4) scores: Q @ K^T -> fp32, lower-triangle tiles only
    dim3 gs(SEQ / BN, SEQ / BM, BATCH);
    gemm_h<0, 1><<<gs, 512, GSMEM>>>(QKV, QKV + D_MODEL, S,
                                     QKV_N, QKV_N, SEQ, D_MODEL,
                                     (long)SEQ * QKV_N, (long)SEQ * QKV_N,
                                     (long)SEQ * SEQ, nullptr);

    // 5) causal softmax -> half probs
    softmax_kernel<<<dim3(SEQ, BATCH), 256>>>();

    // 6) attn_out = P @ Vt^T, fused residual -> half, K truncated at diagonal
    dim3 gp(D_MODEL / BN, SEQ / BM, BATCH);
    gemm_h<2, 2><<<gp, 512, GSMEM>>>(Sh, Vt, X2, SEQ, SEQ, D_MODEL, SEQ,
                                     (long)SEQ * SEQ, (long)D_MODEL * SEQ,
                                     (long)SEQ * D_MODEL, X);

    // 7) logits: X2 @ Wout^T + bias -> fp32
    dim3 gl(VOCAB / BN, M_TOT / BM, 1);
    gemm_h<3, 0><<<gl, 512, GSMEM>>>(X2, Wo, d_out, D_MODEL, D_MODEL, VOCAB, D_MODEL,
                                     0, 0, 0, Wb);
}

// round 6
// speedup vs baseline: 8.7452x; 1.6681x over previous
#include <cuda_runtime.h>
#include <cuda_fp16.h>
#include <cstdint>
#include <cstddef>

#define D_MODEL 1024
#define VOCAB   32000
#define BATCH   4
#define SEQ     2048
#define M_TOT   8192
#define QKV_N   3072
#define RESID_SCALE 0.1f
#define SOFTMAX_SCALE 0.03125f         // 1/sqrt(1024)

// ---------------- scratch (device globals; no allocation) ----------------
__device__ float  g_X  [M_TOT * D_MODEL];            // fp32 embeddings (residual)
__device__ __half g_Xh [M_TOT * D_MODEL];            // half embeddings (GEMM A)
__device__ __half g_QKV[(size_t)M_TOT * QKV_N];      // half Q|K|V
__device__ __half g_Vt [M_TOT * D_MODEL];            // V^T per batch [D_MODEL][SEQ]
__device__ float  g_S  [(size_t)BATCH * SEQ * SEQ];  // fp32 raw scores
__device__ __half g_Sh [(size_t)BATCH * SEQ * SEQ];  // half probs
__device__ __half g_X2 [M_TOT * D_MODEL];            // half (logits A)
__device__ __half g_Wr [QKV_N * D_MODEL];            // half Wq|Wk|Wv stacked
__device__ __half g_Wo [(size_t)VOCAB * D_MODEL];    // half Wout

// ---------------- helpers ----------------
__device__ __forceinline__ uint32_t s2u(const void* p) {
    uint32_t a;
    asm("{ .reg .u64 t; cvta.to.shared.u64 t, %1; cvt.u32.u64 %0, t; }" : "=r"(a) : "l"(p));
    return a;
}
__device__ __forceinline__ uint32_t swz(uint32_t off) {   // SW128
    return off ^ ((off >> 3) & 0x70);
}
__device__ __forceinline__ void cp16(uint32_t dst, const void* src) {
    asm volatile("cp.async.cg.shared.global [%0], [%1], 16;" :: "r"(dst), "l"(src));
}
#define LDSM4(r, addr) \
    asm volatile("ldmatrix.sync.aligned.m8n8.x4.shared.b16 {%0,%1,%2,%3}, [%4];" \
                 : "=r"((r)[0]), "=r"((r)[1]), "=r"((r)[2]), "=r"((r)[3]) : "r"(addr))

__device__ __forceinline__ void mma_f16(float c[4], const uint32_t a[4],
                                        uint32_t b0, uint32_t b1) {
    asm volatile(
        "mma.sync.aligned.m16n8k16.row.col.f32.f16.f16.f32 "
        "{%0,%1,%2,%3}, {%4,%5,%6,%7}, {%8,%9}, {%0,%1,%2,%3};\n"
        : "+f"(c[0]), "+f"(c[1]), "+f"(c[2]), "+f"(c[3])
        : "r"(a[0]), "r"(a[1]), "r"(a[2]), "r"(a[3]), "r"(b0), "r"(b1));
}

// ---------------- small kernels ----------------
__global__ void round_kernel(const float* __restrict__ in, __half* __restrict__ out, int n4) {
    int i = blockIdx.x * blockDim.x + threadIdx.x;
    if (i < n4) {
        float4 v = ((const float4*)in)[i];
        __half2* o = (__half2*)(out + (size_t)i * 4);
        o[0] = __floats2half2_rn(v.x, v.y);
        o[1] = __floats2half2_rn(v.z, v.w);
    }
}

__global__ void embed_kernel(const int* __restrict__ idx,
                             const float* __restrict__ tok,
                             const float* __restrict__ pos) {
    int row = blockIdx.x;
    int t   = row & (SEQ - 1);
    int token = idx[row];
    const float4* te = (const float4*)(tok + (size_t)token * D_MODEL);
    const float4* pe = (const float4*)(pos + (size_t)t * D_MODEL);
    float4*  ox = (float4*)(g_X + (size_t)row * D_MODEL);
    __half2* oh = (__half2*)(g_Xh + (size_t)row * D_MODEL);
    for (int i = threadIdx.x; i < D_MODEL / 4; i += blockDim.x) {
        float4 a = te[i], b = pe[i];
        float4 v = make_float4(a.x + b.x, a.y + b.y, a.z + b.z, a.w + b.w);
        ox[i] = v;
        oh[i * 2]     = __floats2half2_rn(v.x, v.y);
        oh[i * 2 + 1] = __floats2half2_rn(v.z, v.w);
    }
}

// V slice of g_QKV [SEQ, QKV_N] -> Vt [D_MODEL, SEQ] per batch (half)
__global__ void transpose_kernel() {
    __shared__ __half t[32][34];
    int b  = blockIdx.z;
    int t0 = blockIdx.y * 32;   // seq
    int d0 = blockIdx.x * 32;   // dmodel
    const __half* src = g_QKV + (size_t)b * SEQ * QKV_N + 2 * D_MODEL;
    __half*       dst = g_Vt  + (size_t)b * D_MODEL * SEQ;
    int tx = threadIdx.x, ty = threadIdx.y;   // 32 x 8
#pragma unroll
    for (int j = 0; j < 32; j += 8)
        t[ty + j][tx] = src[(size_t)(t0 + ty + j) * QKV_N + d0 + tx];
    __syncthreads();
#pragma unroll
    for (int j = 0; j < 32; j += 8)
        dst[(size_t)(d0 + ty + j) * SEQ + t0 + tx] = t[tx][ty + j];
}

__global__ void softmax_kernel() {
    const int i = blockIdx.x;
    const int b = blockIdx.y;
    const float* s = g_S  + ((size_t)b * SEQ + i) * SEQ;
    __half*     so = g_Sh + ((size_t)b * SEQ + i) * SEQ;
    const int n = i + 1;
    const int tid = threadIdx.x;
    __shared__ float red[256];

    float mx = -3.4e38f;
    for (int j = tid; j < n; j += 256) mx = fmaxf(mx, s[j]);
    red[tid] = mx; __syncthreads();
    for (int o = 128; o > 0; o >>= 1) {
        if (tid < o) red[tid] = fmaxf(red[tid], red[tid + o]);
        __syncthreads();
    }
    mx = red[0];
    __syncthreads();

    float sum = 0.f;
    for (int j = tid; j < n; j += 256) sum += __expf((s[j] - mx) * SOFTMAX_SCALE);
    red[tid] = sum; __syncthreads();
    for (int o = 128; o > 0; o >>= 1) {
        if (tid < o) red[tid] += red[tid + o];
        __syncthreads();
    }
    const float rinv = 1.f / red[0];
    __syncthreads();

    for (int j = tid; j < SEQ; j += 256)
        so[j] = (j < n) ? __float2half_rn(__expf((s[j] - mx) * SOFTMAX_SCALE) * rinv)
                        : __half(0.f);
}

// ---------------- FP16 mma.sync GEMM, 3-stage cp.async + ldmatrix, 2 CTAs/SM ----------------
// C[M,N] = A[M,K] @ B[N,K]^T, A/B half K-major.
// EPI: 0 fp32 out | 1 half out | 2 half out, residual from extra(fp32) | 3 fp32 out + bias
// CAUSAL: 0 none | 1 skip tiles above diagonal | 2 K-limit at diagonal
constexpr int BM = 128, BN = 128, BK = 64;          // BK halves = 128B SW128 row
constexpr int A_BYTES = BM * 128;                   // 16 KB
constexpr int B_BYTES = BN * 128;                   // 16 KB
constexpr int STG = A_BYTES + B_BYTES;              // 32 KB
constexpr int GSMEM = 3 * STG;                      // 96 KB

template<int EPI, int CAUSAL>
__global__ void __launch_bounds__(256, 2)
gemm_h(const __half* __restrict__ A, const __half* __restrict__ B, void* __restrict__ Cv,
       int lda, int ldb, int ldc, int kLen,
       long sA, long sB, long sC, const float* __restrict__ extra) {
    extern __shared__ char smem[];
    const int bz = blockIdx.z;
    const int rowBase = blockIdx.y * BM;
    const int colBase = blockIdx.x * BN;
    if (CAUSAL == 1 && colBase > rowBase + BM - 1) return;

    const __half* Ab = A + sA * bz;
    const __half* Bb = B + sB * bz;

    const int numK = (CAUSAL == 2 ? (rowBase + BM) : kLen) / BK;
    const uint32_t sb = s2u(smem);
    const int tid = threadIdx.x, lane = tid & 31, warp = tid >> 5;
    const int wm = warp >> 2, wn = warp & 3;   // 2 x 4 warps, warp tile 64x32

    const int cr = tid >> 3;    // 0..31
    const int cc = tid & 7;     // 0..7 (16B chunk)

    auto issue = [&](int kt) {
        const uint32_t st = sb + (kt % 3) * STG;
        const int k0 = kt * BK;
        const __half* as = Ab + (size_t)(rowBase + cr) * lda + k0 + cc * 8;
        const __half* bs = Bb + (size_t)(colBase + cr) * ldb + k0 + cc * 8;
#pragma unroll
        for (int j = 0; j < 4; j++) {
            uint32_t so = swz((cr + j * 32) * 128 + cc * 16);
            cp16(st + so,           as + (size_t)j * 32 * lda);
            cp16(st + A_BYTES + so, bs + (size_t)j * 32 * ldb);
        }
        asm volatile("cp.async.commit_group;");
    };

    // ldmatrix per-lane base offsets (pre-swizzle)
    const uint32_t aoff = (uint32_t)((wm * 64 + (lane & 15)) * 128 + (lane >> 4) * 16);
    const uint32_t boff = (uint32_t)((wn * 32 + (lane & 7) + ((lane >> 4) & 1) * 8) * 128
                                     + ((lane >> 3) & 1) * 16);

    float acc[4][4][4];
#pragma unroll
    for (int mi = 0; mi < 4; mi++)
#pragma unroll
        for (int ni = 0; ni < 4; ni++)
#pragma unroll
            for (int r = 0; r < 4; r++) acc[mi][ni][r] = 0.f;

    issue(0);
    if (numK > 1) issue(1);
    if (numK > 2) issue(2);

    for (int kt = 0; kt < numK; kt++) {
        const int rem = numK - kt - 1;
        if (rem >= 2)      asm volatile("cp.async.wait_group 2;");
        else if (rem == 1) asm volatile("cp.async.wait_group 1;");
        else               asm volatile("cp.async.wait_group 0;");
        __syncthreads();

        const uint32_t stA = sb + (kt % 3) * STG;
        const uint32_t stB = stA + A_BYTES;
#pragma unroll
        for (int ks = 0; ks < 4; ks++) {
            uint32_t a[4][4];
#pragma unroll
            for (int mi = 0; mi < 4; mi++)
                LDSM4(a[mi], stA + swz(aoff + mi * 2048 + ks * 32));
            uint32_t bq[2][4];
#pragma unroll
            for (int p = 0; p < 2; p++)
                LDSM4(bq[p], stB + swz(boff + p * 2048 + ks * 32));
#pragma unroll
            for (int mi = 0; mi < 4; mi++) {
                mma_f16(acc[mi][0], a[mi], bq[0][0], bq[0][1]);
                mma_f16(acc[mi][1], a[mi], bq[0][2], bq[0][3]);
                mma_f16(acc[mi][2], a[mi], bq[1][0], bq[1][1]);
                mma_f16(acc[mi][3], a[mi], bq[1][2], bq[1][3]);
            }
        }
        __syncthreads();
        if (kt + 3 < numK) issue(kt + 3);
    }

    // epilogue
    const int gr = lane >> 2, gc = lane & 3;
#pragma unroll
    for (int mi = 0; mi < 4; mi++) {
#pragma unroll
        for (int ni = 0; ni < 4; ni++) {
            int row = rowBase + wm * 64 + mi * 16 + gr;
            int col = colBase + wn * 32 + ni * 8 + gc * 2;
            float v0 = acc[mi][ni][0], v1 = acc[mi][ni][1];
            float v2 = acc[mi][ni][2], v3 = acc[mi][ni][3];
            if (EPI == 0) {
                float* Cb = (float*)Cv + sC * bz;
                *(float2*)(Cb + (size_t)row * ldc + col)       = make_float2(v0, v1);
                *(float2*)(Cb + (size_t)(row + 8) * ldc + col) = make_float2(v2, v3);
            } else if (EPI == 1) {
                __half* Cb = (__half*)Cv + sC * bz;
                *(__half2*)(Cb + (size_t)row * ldc + col)       = __floats2half2_rn(v0, v1);
                *(__half2*)(Cb + (size_t)(row + 8) * ldc + col) = __floats2half2_rn(v2, v3);
            } else if (EPI == 2) {
                __half* Cb = (__half*)Cv + sC * bz;
                const float* x0 = extra + sC * bz + (size_t)row * ldc + col;
                float2 r0 = *(const float2*)x0;
                float2 r1 = *(const float2*)(x0 + (size_t)8 * ldc);
                *(__half2*)(Cb + (size_t)row * ldc + col) =
                    __floats2half2_rn(fmaf(RESID_SCALE, v0, r0.x), fmaf(RESID_SCALE, v1, r0.y));
                *(__half2*)(Cb + (size_t)(row + 8) * ldc + col) =
                    __floats2half2_rn(fmaf(RESID_SCALE, v2, r1.x), fmaf(RESID_SCALE, v3, r1.y));
            } else {
                float* Cb = (float*)Cv + sC * bz;
                float2 bb = *(const float2*)(extra + col);
                *(float2*)(Cb + (size_t)row * ldc + col)       = make_float2(v0 + bb.x, v1 + bb.y);
                *(float2*)(Cb + (size_t)(row + 8) * ldc + col) = make_float2(v2 + bb.x, v3 + bb.y);
            }
        }
    }
}

// ---------------- launch ----------------
extern "C" void kernel_launch(void* const* d_in, const int* in_sizes, int n_in,
                              void* d_out, int out_size) {
    const int*   idx  = (const int*)  d_in[0];
    const float* tok  = (const float*)d_in[1];
    const float* pos  = (const float*)d_in[2];
    const float* Wq   = (const float*)d_in[3];
    const float* Wk   = (const float*)d_in[4];
    const float* Wv   = (const float*)d_in[5];
    const float* Wout = (const float*)d_in[6];
    const float* Wb   = (const float*)d_in[7];

    float *X, *S;
    __half *Xh, *QKV, *Vt, *Sh, *X2, *Wr, *Wo;
    cudaGetSymbolAddress((void**)&X,   g_X);
    cudaGetSymbolAddress((void**)&Xh,  g_Xh);
    cudaGetSymbolAddress((void**)&QKV, g_QKV);
    cudaGetSymbolAddress((void**)&Vt,  g_Vt);
    cudaGetSymbolAddress((void**)&S,   g_S);
    cudaGetSymbolAddress((void**)&Sh,  g_Sh);
    cudaGetSymbolAddress((void**)&X2,  g_X2);
    cudaGetSymbolAddress((void**)&Wr,  g_Wr);
    cudaGetSymbolAddress((void**)&Wo,  g_Wo);

    cudaFuncSetAttribute(gemm_h<1, 0>, cudaFuncAttributeMaxDynamicSharedMemorySize, GSMEM);
    cudaFuncSetAttribute(gemm_h<0, 1>, cudaFuncAttributeMaxDynamicSharedMemorySize, GSMEM);
    cudaFuncSetAttribute(gemm_h<2, 2>, cudaFuncAttributeMaxDynamicSharedMemorySize, GSMEM);
    cudaFuncSetAttribute(gemm_h<3, 0>, cudaFuncAttributeMaxDynamicSharedMemorySize, GSMEM);

    // 0) weights -> half
    const int wn4 = D_MODEL * D_MODEL / 4;
    round_kernel<<<(wn4 + 255) / 256, 256>>>(Wq, Wr,                         wn4);
    round_kernel<<<(wn4 + 255) / 256, 256>>>(Wk, Wr +     D_MODEL * D_MODEL, wn4);
    round_kernel<<<(wn4 + 255) / 256, 256>>>(Wv, Wr + 2 * D_MODEL * D_MODEL, wn4);
    const int on4 = VOCAB * D_MODEL / 4;
    round_kernel<<<(on4 + 255) / 256, 256>>>(Wout, Wo, on4);

    // 1) embeddings
    embed_kernel<<<M_TOT, 256>>>(idx, tok, pos);

    // 2) fused QKV: [8192,1024] @ [3072,1024]^T -> half
    dim3 gq(QKV_N / BN, M_TOT / BM, 1);
    gemm_h<1, 0><<<gq, 256, GSMEM>>>(Xh, Wr, QKV, D_MODEL, D_MODEL, QKV_N, D_MODEL,
                                     0, 0, 0, nullptr);

    // 3) V transpose per batch
    transpose_kernel<<<dim3(D_MODEL / 32, SEQ / 32, BATCH), dim3(32, 8)>>>();

    // 4) scores: Q @ K^T -> fp32, lower-triangle tiles only
    dim3 gs(SEQ / BN, SEQ / BM, BATCH);
    gemm_h<0, 1><<<gs, 256, GSMEM>>>(QKV, QKV + D_MODEL, S,
                                     QKV_N, QKV_N, SEQ, D_MODEL,
                                     (long)SEQ * QKV_N, (long)SEQ * QKV_N,
                                     (long)SEQ * SEQ, nullptr);

    // 5) causal softmax -> half probs
    softmax_kernel<<<dim3(SEQ, BATCH), 256>>>();

    // 6) attn_out = P @ Vt^T, fused residual -> half, K truncated at diagonal
    dim3 gp(D_MODEL / BN, SEQ / BM, BATCH);
    gemm_h<2, 2><<<gp, 256, GSMEM>>>(Sh, Vt, X2, SEQ, SEQ, D_MODEL, SEQ,
                                     (long)SEQ * SEQ, (long)D_MODEL * SEQ,
                                     (long)SEQ * D_MODEL, X);

    // 7) logits: X2 @ Wout^T + bias -> fp32
    dim3 gl(VOCAB / BN, M_TOT / BM, 1);
    gemm_h<3, 0><<<gl, 256, GSMEM>>>(X2, Wo, d_out, D_MODEL, D_MODEL, VOCAB, D_MODEL,
                                     0, 0, 0, Wb);
}